// round 1
// baseline (speedup 1.0000x reference)
#include <cuda_runtime.h>

// Problem constants
#define BB 32
#define TT 64
#define NN 207
#define FF 64
#define HH 128
#define MM (BB * NN)      // 6624
#define G3 (3 * HH)       // 384

// Ping-pong hidden state buffers (scratch: __device__ globals, no allocs)
__device__ float g_h0[2][MM * HH];
__device__ float g_h1[2][MM * HH];

__global__ void zero_states_kernel() {
    int i = blockIdx.x * blockDim.x + threadIdx.x;
    if (i < MM * HH) {
        g_h0[0][i] = 0.0f;
        g_h1[0][i] = 0.0f;
    }
}

__device__ __forceinline__ float sigmoidf_(float x) {
    return 1.0f / (1.0f + expf(-x));
}

// Fused GRU step for one layer, one timestep.
//   gi = X @ Wih + bih   (K = KA)
//   gh = Hin @ Whh + bhh (K = HH)
//   r = sig(gi_r + gh_r); z = sig(gi_z + gh_z); n = tanh(gi_n + r*gh_n)
//   Hout = (1-z)*n + z*Hin      (also written to Oout[:, t] if Oout != null)
//
// Tile: BM=64 rows x 32 hidden cols (=> 96 gate cols), K chunked by 64.
// 256 threads, each computes 4 rows x 2 cols x 3 gates per GEMM.
template <int KA, bool XTIME>
__global__ void __launch_bounds__(256)
gru_step_kernel(const float* __restrict__ X,
                const float* __restrict__ Wih, const float* __restrict__ bih,
                const float* __restrict__ Hin,
                const float* __restrict__ Whh, const float* __restrict__ bhh,
                float* __restrict__ Hout,
                float* __restrict__ Oout,
                int t)
{
    __shared__ float As[64][68];   // activation chunk [BM][BK], padded
    __shared__ float Ws[64][96];   // weight chunk [BK][3*32]

    const int tid = threadIdx.x;
    const int tx  = tid & 15;      // 0..15  -> 2 hidden cols each
    const int ty  = tid >> 4;      // 0..15  -> 4 rows each
    const int m0  = blockIdx.x * 64;
    const int j0  = blockIdx.y * 32;

    float acc_i[3][4][2];
    float acc_h[3][4][2];
#pragma unroll
    for (int g = 0; g < 3; g++)
#pragma unroll
        for (int i = 0; i < 4; i++) {
            acc_i[g][i][0] = 0.f; acc_i[g][i][1] = 0.f;
            acc_h[g][i][0] = 0.f; acc_h[g][i][1] = 0.f;
        }

    // ---------------- Phase 1: gi = X @ Wih ----------------
    const int NCHUNK_I = KA / 64;
#pragma unroll
    for (int kc = 0; kc < NCHUNK_I; kc++) {
        // load X chunk [64 rows][64 cols]
#pragma unroll
        for (int l = 0; l < 4; l++) {
            int lin = tid + l * 256;          // 0..1023
            int row = lin >> 4;               // /16 float4 per row
            int c4  = (lin & 15) << 2;
            int gm  = m0 + row;
            float4 v = make_float4(0.f, 0.f, 0.f, 0.f);
            if (gm < MM) {
                int col = kc * 64 + c4;
                const float* src;
                if (XTIME) {
                    int b = gm / NN;
                    int n = gm - b * NN;
                    src = X + (size_t)((b * TT + t) * NN + n) * FF + col;
                } else {
                    src = X + (size_t)gm * KA + col;
                }
                v = *(const float4*)src;
            }
            *(float4*)&As[row][c4] = v;
        }
        // load Wih chunk [64 rows][96 gate cols]
#pragma unroll
        for (int l = 0; l < 6; l++) {
            int lin = tid + l * 256;          // 0..1535
            int row = lin / 24;
            int cc  = (lin - row * 24) * 4;   // 0..92
            int g   = cc >> 5;
            int c   = cc & 31;
            float4 v = *(const float4*)&Wih[(size_t)(kc * 64 + row) * G3 + g * HH + j0 + c];
            *(float4*)&Ws[row][cc] = v;
        }
        __syncthreads();

#pragma unroll 8
        for (int k = 0; k < 64; k++) {
            float a0 = As[ty * 4 + 0][k];
            float a1 = As[ty * 4 + 1][k];
            float a2 = As[ty * 4 + 2][k];
            float a3 = As[ty * 4 + 3][k];
#pragma unroll
            for (int g = 0; g < 3; g++) {
                float2 w = *(const float2*)&Ws[k][g * 32 + tx * 2];
                acc_i[g][0][0] += a0 * w.x; acc_i[g][0][1] += a0 * w.y;
                acc_i[g][1][0] += a1 * w.x; acc_i[g][1][1] += a1 * w.y;
                acc_i[g][2][0] += a2 * w.x; acc_i[g][2][1] += a2 * w.y;
                acc_i[g][3][0] += a3 * w.x; acc_i[g][3][1] += a3 * w.y;
            }
        }
        __syncthreads();
    }

    // ---------------- Phase 2: gh = Hin @ Whh ----------------
#pragma unroll
    for (int kc = 0; kc < 2; kc++) {
#pragma unroll
        for (int l = 0; l < 4; l++) {
            int lin = tid + l * 256;
            int row = lin >> 4;
            int c4  = (lin & 15) << 2;
            int gm  = m0 + row;
            float4 v = make_float4(0.f, 0.f, 0.f, 0.f);
            if (gm < MM) {
                int col = kc * 64 + c4;
                v = *(const float4*)&Hin[(size_t)gm * HH + col];
            }
            *(float4*)&As[row][c4] = v;
        }
#pragma unroll
        for (int l = 0; l < 6; l++) {
            int lin = tid + l * 256;
            int row = lin / 24;
            int cc  = (lin - row * 24) * 4;
            int g   = cc >> 5;
            int c   = cc & 31;
            float4 v = *(const float4*)&Whh[(size_t)(kc * 64 + row) * G3 + g * HH + j0 + c];
            *(float4*)&Ws[row][cc] = v;
        }
        __syncthreads();

#pragma unroll 8
        for (int k = 0; k < 64; k++) {
            float a0 = As[ty * 4 + 0][k];
            float a1 = As[ty * 4 + 1][k];
            float a2 = As[ty * 4 + 2][k];
            float a3 = As[ty * 4 + 3][k];
#pragma unroll
            for (int g = 0; g < 3; g++) {
                float2 w = *(const float2*)&Ws[k][g * 32 + tx * 2];
                acc_h[g][0][0] += a0 * w.x; acc_h[g][0][1] += a0 * w.y;
                acc_h[g][1][0] += a1 * w.x; acc_h[g][1][1] += a1 * w.y;
                acc_h[g][2][0] += a2 * w.x; acc_h[g][2][1] += a2 * w.y;
                acc_h[g][3][0] += a3 * w.x; acc_h[g][3][1] += a3 * w.y;
            }
        }
        __syncthreads();
    }

    // ---------------- Epilogue: GRU cell + writes ----------------
    const int j = j0 + tx * 2;
    const float2 br_i = *(const float2*)&bih[0 * HH + j];
    const float2 bz_i = *(const float2*)&bih[1 * HH + j];
    const float2 bn_i = *(const float2*)&bih[2 * HH + j];
    const float2 br_h = *(const float2*)&bhh[0 * HH + j];
    const float2 bz_h = *(const float2*)&bhh[1 * HH + j];
    const float2 bn_h = *(const float2*)&bhh[2 * HH + j];

#pragma unroll
    for (int i = 0; i < 4; i++) {
        int gm = m0 + ty * 4 + i;
        if (gm >= MM) continue;

        float2 hprev = *(const float2*)&Hin[(size_t)gm * HH + j];

        float hv[2];
#pragma unroll
        for (int ci = 0; ci < 2; ci++) {
            float ir = acc_i[0][i][ci] + (ci ? br_i.y : br_i.x);
            float iz = acc_i[1][i][ci] + (ci ? bz_i.y : bz_i.x);
            float in_ = acc_i[2][i][ci] + (ci ? bn_i.y : bn_i.x);
            float hr = acc_h[0][i][ci] + (ci ? br_h.y : br_h.x);
            float hz = acc_h[1][i][ci] + (ci ? bz_h.y : bz_h.x);
            float hn = acc_h[2][i][ci] + (ci ? bn_h.y : bn_h.x);
            float r = sigmoidf_(ir + hr);
            float z = sigmoidf_(iz + hz);
            float n = tanhf(in_ + r * hn);
            float hp = ci ? hprev.y : hprev.x;
            hv[ci] = (1.0f - z) * n + z * hp;
        }
        float2 hv2 = make_float2(hv[0], hv[1]);
        *(float2*)&Hout[(size_t)gm * HH + j] = hv2;
        if (Oout) {
            int b = gm / NN;
            int n = gm - b * NN;
            *(float2*)&Oout[(size_t)((b * TT + t) * NN + n) * HH + j] = hv2;
        }
    }
}

extern "C" void kernel_launch(void* const* d_in, const int* in_sizes, int n_in,
                              void* d_out, int out_size)
{
    const float* x    = (const float*)d_in[0];
    const float* Wih0 = (const float*)d_in[1];
    const float* Whh0 = (const float*)d_in[2];
    const float* bih0 = (const float*)d_in[3];
    const float* bhh0 = (const float*)d_in[4];
    const float* Wih1 = (const float*)d_in[5];
    const float* Whh1 = (const float*)d_in[6];
    const float* bih1 = (const float*)d_in[7];
    const float* bhh1 = (const float*)d_in[8];

    float* out = (float*)d_out;
    float* h0f = out + (size_t)BB * TT * NN * HH;
    float* h1f = h0f + (size_t)BB * NN * HH;

    float *h0p = nullptr, *h1p = nullptr;
    cudaGetSymbolAddress((void**)&h0p, g_h0);
    cudaGetSymbolAddress((void**)&h1p, g_h1);
    const size_t SH = (size_t)MM * HH;

    zero_states_kernel<<<(MM * HH + 255) / 256, 256>>>();

    dim3 grid((MM + 63) / 64, HH / 32);
    for (int t = 0; t < TT; t++) {
        int cur = t & 1;
        int nxt = cur ^ 1;
        gru_step_kernel<64, true><<<grid, 256>>>(
            x, Wih0, bih0,
            h0p + cur * SH, Whh0, bhh0,
            h0p + nxt * SH, (float*)nullptr, t);
        gru_step_kernel<128, false><<<grid, 256>>>(
            h0p + nxt * SH, Wih1, bih1,
            h1p + cur * SH, Whh1, bhh1,
            h1p + nxt * SH, out, t);
    }
    // After t=63, the freshly written states live in buffer index 0.
    cudaMemcpyAsync(h0f, h0p, SH * sizeof(float), cudaMemcpyDeviceToDevice);
    cudaMemcpyAsync(h1f, h1p, SH * sizeof(float), cudaMemcpyDeviceToDevice);
}

// round 5
// speedup vs baseline: 1.3361x; 1.3361x over previous
#include <cuda_runtime.h>
#include <cstdint>

#define BB 32
#define TT 64
#define NNODE 207
#define FF 64
#define HH 128
#define MM (BB * NNODE)      // 6624
#define MTILE 96
#define GRIDM (MM / MTILE)   // 69
#define NTH 384

// -------- scratch (device globals; no allocs) --------
__device__ float g_h0[2][MM * HH];
__device__ float g_h1[2][MM * HH];

// packed tf32 hi/lo weights, fragment-native layout:
// region layout: [kstep][48 ntile][2 hilo][64 floats]  (64 = 32 lanes x 2)
#define WP_L0IH 0
#define WP_L0HH (64 * 384 * 2)
#define WP_L1IH (WP_L0HH + 128 * 384 * 2)
#define WP_L1HH (WP_L1IH + 128 * 384 * 2)
#define WP_TOTAL (WP_L1HH + 128 * 384 * 2)
__device__ float g_wp[WP_TOTAL];

__device__ __forceinline__ float tf32r(float x) {
    unsigned int y;
    asm("cvt.rna.tf32.f32 %0, %1;" : "=r"(y) : "f"(x));
    return __uint_as_float(y);
}

// ---------------- weight prepack ----------------
// Packed gate-column permutation: packed col p (0..383):
//   w16 = p/48  (16-wide j block, 0..7)
//   g   = (p%48)/16  (gate r/z/n)
//   jj  = p%16
//   original col = g*128 + w16*16 + jj
// => each warp (48 packed cols) owns complete (r,z,n) triples for 16 j's.
__global__ void prep_kernel(const float* __restrict__ Wih0, const float* __restrict__ Whh0,
                            const float* __restrict__ Wih1, const float* __restrict__ Whh1)
{
    const float* srcs[4] = {Wih0, Whh0, Wih1, Whh1};
    const int Ks[4]   = {64, 128, 128, 128};
    const int offs[4] = {WP_L0IH, WP_L0HH, WP_L1IH, WP_L1HH};
    const int total = (64 + 128 + 128 + 128) * 384;
    for (int idx = blockIdx.x * blockDim.x + threadIdx.x; idx < total;
         idx += gridDim.x * blockDim.x) {
        int m, rem = idx;
        for (m = 0; m < 4; m++) {
            int sz = Ks[m] * 384;
            if (rem < sz) break;
            rem -= sz;
        }
        int k = rem / 384;
        int p = rem % 384;
        int w16 = p / 48;
        int g = (p % 48) / 16;
        int jj = p % 16;
        float v = srcs[m][(size_t)k * 384 + g * 128 + w16 * 16 + jj];
        float hi = tf32r(v);
        float lo = tf32r(v - hi);
        // frag position: lane = (p%8)*4 + (k%4); b0/b1 slot = (k/4)%2
        int a = ((k >> 3) * 48 + (p >> 3)) * 2;
        int lane2 = ((p & 7) * 4 + (k & 3)) * 2 + ((k >> 2) & 1);
        g_wp[offs[m] + (size_t)(a + 0) * 64 + lane2] = hi;
        g_wp[offs[m] + (size_t)(a + 1) * 64 + lane2] = lo;
    }
}

__global__ void zero_states_kernel() {
    int i = blockIdx.x * blockDim.x + threadIdx.x;
    if (i < MM * HH) {
        g_h0[0][i] = 0.0f;
        g_h1[0][i] = 0.0f;
    }
}

#define MMA_T(D, A, B)                                                            \
    asm volatile(                                                                 \
        "mma.sync.aligned.m16n8k8.row.col.f32.tf32.tf32.f32 "                     \
        "{%0,%1,%2,%3},{%4,%5,%6,%7},{%8,%9},{%0,%1,%2,%3};\n"                    \
        : "+f"(D[0]), "+f"(D[1]), "+f"(D[2]), "+f"(D[3])                          \
        : "r"(A.x), "r"(A.y), "r"(A.z), "r"(A.w), "r"(B.x), "r"(B.y))

// ---------------- fused GRU layer step ----------------
// grid (69, 2): block = 96 rows x 64 h-cols (=192 packed gate cols).
// 384 threads = 12 warps as 3(m) x 4(n); warp tile: 32 rows x 48 packed cols
// = (r,z,n) x 16 j-cols. Epilogue is fully register-resident per warp.
// A is staged through 48KB static smem in chunks of 8 ksteps (64 k-values).
template <int KX, bool XTIME, bool WRITE_OUT>
__global__ void __launch_bounds__(NTH, 1)
gru_layer(const float* __restrict__ Xsrc, const float* __restrict__ Hin,
          float* __restrict__ Hout, float* __restrict__ Oout,
          const float* __restrict__ wih_p, const float* __restrict__ whh_p,
          const float* __restrict__ bih, const float* __restrict__ bhh, int t)
{
    // [t2 = ksl*6 + mtile][hilo][128 floats]  : 8*6*2*128 = 12288 floats = 48KB
    __shared__ float smem[8 * 6 * 2 * 128];

    const int KSX = KX / 8;                // input ksteps (8 or 16)
    const int tid = threadIdx.x;
    const int mb = blockIdx.x * MTILE;
    const int half = blockIdx.y;

    const int wid = tid >> 5, lane = tid & 31;
    const int wm = wid >> 2;               // 0..2 -> 32-row strip
    const int wn = wid & 3;                // 0..3 -> 48-col strip
    const int ntb = half * 24 + wn * 6;    // global ntile base for this warp

    float acc0[2][6][4];                   // gi
    float acc1[2][6][4];                   // gh
#pragma unroll
    for (int m = 0; m < 2; m++)
#pragma unroll
        for (int n = 0; n < 6; n++)
#pragma unroll
            for (int c = 0; c < 4; c++) { acc0[m][n][c] = 0.f; acc1[m][n][c] = 0.f; }

    // ---- chunk loader: global kstep base = cks*8 ----
    auto load_chunk = [&](int cks) {
#pragma unroll 1
        for (int s = tid; s < 1536; s += NTH) {
            int ln = s & 31;
            int t2 = s >> 5;               // 0..47
            int mt = t2 % 6;
            int ksl = t2 / 6;              // 0..7
            int ks = cks * 8 + ksl;
            int r0 = mt * 16 + (ln >> 2);
            int c0 = ln & 3;
            int gm0 = mb + r0, gm1 = gm0 + 8;
            float v00, v01, v10, v11;
            if (ks < KSX) {
                int k0 = ks * 8 + c0, k1 = k0 + 4;
                if (XTIME) {
                    int b0 = gm0 / NNODE, n0 = gm0 - b0 * NNODE;
                    int b1 = gm1 / NNODE, n1 = gm1 - b1 * NNODE;
                    const float* p0 = Xsrc + (size_t)((b0 * TT + t) * NNODE + n0) * FF;
                    const float* p1 = Xsrc + (size_t)((b1 * TT + t) * NNODE + n1) * FF;
                    v00 = p0[k0]; v01 = p0[k1];
                    v10 = p1[k0]; v11 = p1[k1];
                } else {
                    v00 = Xsrc[(size_t)gm0 * KX + k0]; v01 = Xsrc[(size_t)gm0 * KX + k1];
                    v10 = Xsrc[(size_t)gm1 * KX + k0]; v11 = Xsrc[(size_t)gm1 * KX + k1];
                }
            } else {
                int k0 = (ks - KSX) * 8 + c0, k1 = k0 + 4;
                v00 = Hin[(size_t)gm0 * HH + k0]; v01 = Hin[(size_t)gm0 * HH + k1];
                v10 = Hin[(size_t)gm1 * HH + k0]; v11 = Hin[(size_t)gm1 * HH + k1];
            }
            float h00 = tf32r(v00), h10 = tf32r(v10), h01 = tf32r(v01), h11 = tf32r(v11);
            *(float4*)(smem + (size_t)(t2 * 2 + 0) * 128 + ln * 4) =
                make_float4(h00, h10, h01, h11);
            *(float4*)(smem + (size_t)(t2 * 2 + 1) * 128 + ln * 4) =
                make_float4(tf32r(v00 - h00), tf32r(v10 - h10),
                            tf32r(v01 - h01), tf32r(v11 - h11));
        }
    };

    // ---- chunk MMA: 8 local ksteps against weight base wp_b, kstep base kb ----
    auto mma_chunk = [&](const float* wp_b, int kb, float (*acc)[6][4]) {
#pragma unroll 2
        for (int ksl = 0; ksl < 8; ksl++) {
            uint4 ah[2], al[2];
#pragma unroll
            for (int m = 0; m < 2; m++) {
                int t2 = ksl * 6 + wm * 2 + m;
                ah[m] = *(const uint4*)(smem + (size_t)(t2 * 2 + 0) * 128 + lane * 4);
                al[m] = *(const uint4*)(smem + (size_t)(t2 * 2 + 1) * 128 + lane * 4);
            }
            uint2 bh[6], bl[6];
#pragma unroll
            for (int n = 0; n < 6; n++) {
                const float* bp = wp_b + (size_t)(((kb + ksl) * 48 + ntb + n) * 2) * 64 + lane * 2;
                bh[n] = *(const uint2*)bp;
                bl[n] = *(const uint2*)(bp + 64);
            }
#pragma unroll
            for (int m = 0; m < 2; m++)
#pragma unroll
                for (int n = 0; n < 6; n++) {
                    MMA_T(acc[m][n], ah[m], bh[n]);
                    MMA_T(acc[m][n], ah[m], bl[n]);
                    MMA_T(acc[m][n], al[m], bh[n]);
                }
        }
    };

    const int NCX = KSX / 8;               // 1 or 2 input chunks
#pragma unroll 1
    for (int c = 0; c < NCX; c++) {
        load_chunk(c);
        __syncthreads();
        mma_chunk(wih_p, c * 8, acc0);
        __syncthreads();
    }
#pragma unroll 1
    for (int c = 0; c < 2; c++) {          // hidden part: 16 ksteps
        load_chunk(NCX + c);
        __syncthreads();
        mma_chunk(whh_p, c * 8, acc1);
        __syncthreads();
    }

    // ---- register-resident GRU cell epilogue ----
    {
        const int w16 = half * 4 + wn;      // 16-wide j block (0..7)
        const int jq = (lane & 3) * 2;      // col pair offset within 8-tile
        const int lane4 = lane >> 2;        // row offset within 16-tile

        // biases for this thread's 4 j's (nb in 0..1, ci in 0..1)
        float bir[2][2], biz[2][2], bin_[2][2];
        float bhr[2][2], bhz[2][2], bhn[2][2];
#pragma unroll
        for (int nb = 0; nb < 2; nb++)
#pragma unroll
            for (int ci = 0; ci < 2; ci++) {
                int j = w16 * 16 + nb * 8 + jq + ci;
                bir[nb][ci] = bih[j];        biz[nb][ci] = bih[128 + j];
                bin_[nb][ci] = bih[256 + j];
                bhr[nb][ci] = bhh[j];        bhz[nb][ci] = bhh[128 + j];
                bhn[nb][ci] = bhh[256 + j];
            }

#pragma unroll
        for (int m = 0; m < 2; m++) {
#pragma unroll
            for (int h8 = 0; h8 < 2; h8++) {      // c-pair: rows lane4 / lane4+8
                int gm = mb + wm * 32 + m * 16 + lane4 + h8 * 8;
                int ob = gm / NNODE;
                int on = gm - ob * NNODE;
                size_t obase = WRITE_OUT ?
                    ((size_t)((ob * TT + t) * NNODE + on) * HH) : 0;
#pragma unroll
                for (int nb = 0; nb < 2; nb++) {
                    int j0 = w16 * 16 + nb * 8 + jq;
                    float2 hp = *(const float2*)&Hin[(size_t)gm * HH + j0];
                    float hv[2];
#pragma unroll
                    for (int ci = 0; ci < 2; ci++) {
                        int c = h8 * 2 + ci;
                        // gates: n-subtiles nb -> r, nb+2 -> z, nb+4 -> n
                        float ir = acc0[m][nb][c]     + bir[nb][ci];
                        float iz = acc0[m][nb + 2][c] + biz[nb][ci];
                        float in_ = acc0[m][nb + 4][c] + bin_[nb][ci];
                        float hr = acc1[m][nb][c]     + bhr[nb][ci];
                        float hz = acc1[m][nb + 2][c] + bhz[nb][ci];
                        float hn = acc1[m][nb + 4][c] + bhn[nb][ci];
                        float r = 1.f / (1.f + __expf(-(ir + hr)));
                        float z = 1.f / (1.f + __expf(-(iz + hz)));
                        float nn = tanhf(in_ + r * hn);
                        float hpv = ci ? hp.y : hp.x;
                        hv[ci] = (1.f - z) * nn + z * hpv;
                    }
                    float2 hv2 = make_float2(hv[0], hv[1]);
                    *(float2*)&Hout[(size_t)gm * HH + j0] = hv2;
                    if (WRITE_OUT)
                        *(float2*)&Oout[obase + j0] = hv2;
                }
            }
        }
    }
}

extern "C" void kernel_launch(void* const* d_in, const int* in_sizes, int n_in,
                              void* d_out, int out_size)
{
    const float* x    = (const float*)d_in[0];
    const float* Wih0 = (const float*)d_in[1];
    const float* Whh0 = (const float*)d_in[2];
    const float* bih0 = (const float*)d_in[3];
    const float* bhh0 = (const float*)d_in[4];
    const float* Wih1 = (const float*)d_in[5];
    const float* Whh1 = (const float*)d_in[6];
    const float* bih1 = (const float*)d_in[7];
    const float* bhh1 = (const float*)d_in[8];

    float* out = (float*)d_out;
    float* h0f = out + (size_t)BB * TT * NNODE * HH;
    float* h1f = h0f + (size_t)MM * HH;

    float *h0p = nullptr, *h1p = nullptr, *wp = nullptr;
    cudaGetSymbolAddress((void**)&h0p, g_h0);
    cudaGetSymbolAddress((void**)&h1p, g_h1);
    cudaGetSymbolAddress((void**)&wp, g_wp);
    const size_t SH = (size_t)MM * HH;

    prep_kernel<<<168, 256>>>(Wih0, Whh0, Wih1, Whh1);
    zero_states_kernel<<<(MM * HH + 255) / 256, 256>>>();

    dim3 grid(GRIDM, 2);
    for (int t = 0; t < TT; t++) {
        int cur = t & 1;
        int nxt = cur ^ 1;
        gru_layer<64, true, false><<<grid, NTH>>>(
            x, h0p + cur * SH, h0p + nxt * SH, (float*)nullptr,
            wp + WP_L0IH, wp + WP_L0HH, bih0, bhh0, t);
        gru_layer<128, false, true><<<grid, NTH>>>(
            h0p + nxt * SH, h1p + cur * SH, h1p + nxt * SH, out,
            wp + WP_L1IH, wp + WP_L1HH, bih1, bhh1, t);
    }
    cudaMemcpyAsync(h0f, h0p, SH * sizeof(float), cudaMemcpyDeviceToDevice);
    cudaMemcpyAsync(h1f, h1p, SH * sizeof(float), cudaMemcpyDeviceToDevice);
}

// round 6
// speedup vs baseline: 2.1550x; 1.6129x over previous
#include <cuda_runtime.h>
#include <cuda_bf16.h>
#include <cstdint>

#define BB 32
#define TT 64
#define NNODE 207
#define FF 64
#define HH 128
#define MM (BB * NNODE)      // 6624
#define MTILE 96
#define GRIDM 69             // 6624 / 96
#define NTH 384

// -------- scratch (device globals; no allocs) --------
__device__ float g_h0[2][MM * HH];
__device__ float g_h1[2][MM * HH];

// packed bf16 hi/lo weights, fragment-native (m16n8k16) layout.
// uint2 unit index: ((k16*48 + ntile)*2 + hilo)*32 + lane ; uint2 = {b0,b1}
// region offsets in uint2 units:
#define WPU2_L0IH 0
#define WPU2_L0HH 12288      // 4*48*2*32
#define WPU2_L1IH 36864      // +8*48*2*32
#define WPU2_L1HH 61440
#define WPU2_TOTAL 86016
__device__ unsigned g_wp[WPU2_TOTAL * 2];

// ---------------- weight prepack ----------------
// packed gate-col permutation: p -> w16=p/48, g=(p%48)/16, jj=p%16
// original col = g*128 + w16*16 + jj
// => each warp (6 ntiles = 48 packed cols) owns (r,z,n) triples for 16 j's.
__global__ void prep_kernel(const float* __restrict__ Wih0, const float* __restrict__ Whh0,
                            const float* __restrict__ Wih1, const float* __restrict__ Whh1)
{
    __nv_bfloat16* wp = reinterpret_cast<__nv_bfloat16*>(g_wp);
    const float* srcs[4] = {Wih0, Whh0, Wih1, Whh1};
    const int Ks[4]   = {64, 128, 128, 128};
    const int offs[4] = {WPU2_L0IH * 4, WPU2_L0HH * 4, WPU2_L1IH * 4, WPU2_L1HH * 4};
    const int total = (64 + 128 + 128 + 128) * 384;
    for (int idx = blockIdx.x * blockDim.x + threadIdx.x; idx < total;
         idx += gridDim.x * blockDim.x) {
        int m, rem = idx;
        for (m = 0; m < 4; m++) {
            int sz = Ks[m] * 384;
            if (rem < sz) break;
            rem -= sz;
        }
        int k = rem / 384;
        int p = rem % 384;
        int w16 = p / 48, g = (p % 48) / 16, jj = p % 16;
        float v = srcs[m][(size_t)k * 384 + g * 128 + w16 * 16 + jj];
        __nv_bfloat16 hb = __float2bfloat16_rn(v);
        __nv_bfloat16 lb = __float2bfloat16_rn(v - __bfloat162float(hb));
        // fragment position (B of m16n8k16, col-major 16x8 tile):
        int k16 = k >> 4, kk = k & 15;
        int nt = p >> 3;
        int lane = (p & 7) * 4 + ((kk & 7) >> 1);
        int slot = kk >> 3;       // b0 / b1
        int hw = kk & 1;          // low/high half of u32
        int ib = (((k16 * 48 + nt) * 2) * 32 + lane) * 4 + slot * 2 + hw;
        wp[offs[m] + ib] = hb;          // hilo=0
        wp[offs[m] + ib + 128] = lb;    // hilo=1 (+32 lanes * 4)
    }
}

__global__ void zero_states_kernel() {
    int i = blockIdx.x * blockDim.x + threadIdx.x;
    if (i < MM * HH) {
        g_h0[0][i] = 0.0f;
        g_h1[0][i] = 0.0f;
    }
}

#define MMA_B(D, A, B)                                                            \
    asm volatile(                                                                 \
        "mma.sync.aligned.m16n8k16.row.col.f32.bf16.bf16.f32 "                    \
        "{%0,%1,%2,%3},{%4,%5,%6,%7},{%8,%9},{%0,%1,%2,%3};\n"                    \
        : "+f"(D[0]), "+f"(D[1]), "+f"(D[2]), "+f"(D[3])                          \
        : "r"(A.x), "r"(A.y), "r"(A.z), "r"(A.w), "r"(B.x), "r"(B.y))

__device__ __forceinline__ void split_pack(float vx, float vy, unsigned& hi, unsigned& lo) {
    __nv_bfloat16 hx = __float2bfloat16_rn(vx);
    __nv_bfloat16 hy = __float2bfloat16_rn(vy);
    __nv_bfloat16 lx = __float2bfloat16_rn(vx - __bfloat162float(hx));
    __nv_bfloat16 ly = __float2bfloat16_rn(vy - __bfloat162float(hy));
    hi = (unsigned)__bfloat16_as_ushort(hx) | ((unsigned)__bfloat16_as_ushort(hy) << 16);
    lo = (unsigned)__bfloat16_as_ushort(lx) | ((unsigned)__bfloat16_as_ushort(ly) << 16);
}

// smem chunk: 4 k16-steps x 6 mtiles x 2 hilo x 128 u32 = 6144 u32 = 24KB
// A-frag native: uint4 per lane = {a0,a1,a2,a3}
template <bool XT>
__device__ __forceinline__ void load_chunk(unsigned* sm, const float* __restrict__ src,
                                           int kbase, int mb, int t, int tid)
{
#pragma unroll
    for (int it = 0; it < 2; it++) {
        int s = tid + it * NTH;          // 0..767
        int ln = s & 31;
        int t2 = s >> 5;                 // ksl*6 + mt
        int mt = t2 % 6, ksl = t2 / 6;
        int r0 = mb + mt * 16 + (ln >> 2);
        int c0 = kbase + ksl * 16 + (ln & 3) * 2;
        const float *p0, *p1;
        if (XT) {
            int b0 = r0 / NNODE, n0 = r0 - b0 * NNODE;
            int r1 = r0 + 8;
            int b1 = r1 / NNODE, n1 = r1 - b1 * NNODE;
            p0 = src + (size_t)((b0 * TT + t) * NNODE + n0) * FF;
            p1 = src + (size_t)((b1 * TT + t) * NNODE + n1) * FF;
        } else {
            p0 = src + (size_t)r0 * HH;
            p1 = p0 + 8 * HH;
        }
        float2 v00 = *(const float2*)(p0 + c0);
        float2 v01 = *(const float2*)(p0 + c0 + 8);
        float2 v10 = *(const float2*)(p1 + c0);
        float2 v11 = *(const float2*)(p1 + c0 + 8);
        unsigned h0, l0, h1, l1, h2, l2, h3, l3;
        split_pack(v00.x, v00.y, h0, l0);   // a0: (r, c0..c0+1)
        split_pack(v10.x, v10.y, h1, l1);   // a1: (r+8, ...)
        split_pack(v01.x, v01.y, h2, l2);   // a2: (r, c0+8..9)
        split_pack(v11.x, v11.y, h3, l3);   // a3
        *(uint4*)(sm + (t2 * 2 + 0) * 128 + ln * 4) = make_uint4(h0, h1, h2, h3);
        *(uint4*)(sm + (t2 * 2 + 1) * 128 + ln * 4) = make_uint4(l0, l1, l2, l3);
    }
}

__device__ __forceinline__ void mma_chunk(const unsigned* sm, const uint2* __restrict__ wb,
                                          int ntb, int wm, int lane, float (*acc)[6][4])
{
#pragma unroll
    for (int ksl = 0; ksl < 4; ksl++) {
        uint4 ah[2], al[2];
#pragma unroll
        for (int m = 0; m < 2; m++) {
            int t2 = ksl * 6 + wm * 2 + m;
            ah[m] = *(const uint4*)(sm + (t2 * 2 + 0) * 128 + lane * 4);
            al[m] = *(const uint4*)(sm + (t2 * 2 + 1) * 128 + lane * 4);
        }
        uint2 bh[6], bl[6];
#pragma unroll
        for (int n = 0; n < 6; n++) {
            int i2 = ((ksl * 48 + ntb + n) * 2) * 32 + lane;
            bh[n] = wb[i2];
            bl[n] = wb[i2 + 32];
        }
#pragma unroll
        for (int m = 0; m < 2; m++)
#pragma unroll
            for (int n = 0; n < 6; n++) {
                MMA_B(acc[m][n], ah[m], bh[n]);
                MMA_B(acc[m][n], ah[m], bl[n]);
                MMA_B(acc[m][n], al[m], bh[n]);
            }
    }
}

// one GRU layer step for this block's 96 rows x 64 h-cols
template <bool XT, bool WOUT>
__device__ __forceinline__ void run_layer(unsigned* sm, const float* __restrict__ Xsrc, int KXc,
    const float* __restrict__ Hin, float* __restrict__ Hout, float* __restrict__ Oout,
    const uint2* __restrict__ wih, const uint2* __restrict__ whh,
    const float* __restrict__ bih, const float* __restrict__ bhh,
    int t, int mb, int half, int wm, int wn, int lane, int tid)
{
    const int ntb = half * 24 + wn * 6;
    float acc0[2][6][4], acc1[2][6][4];
#pragma unroll
    for (int m = 0; m < 2; m++)
#pragma unroll
        for (int n = 0; n < 6; n++)
#pragma unroll
            for (int c = 0; c < 4; c++) { acc0[m][n][c] = 0.f; acc1[m][n][c] = 0.f; }

    const int NC = KXc >> 6;             // 1 or 2 input chunks
#pragma unroll 1
    for (int c = 0; c < NC; c++) {
        load_chunk<XT>(sm, Xsrc, c * 64, mb, t, tid);
        __syncthreads();
        mma_chunk(sm, wih + c * 12288, ntb, wm, lane, acc0);
        __syncthreads();
    }
#pragma unroll 1
    for (int c = 0; c < 2; c++) {
        load_chunk<false>(sm, Hin, c * 64, mb, t, tid);
        __syncthreads();
        mma_chunk(sm, whh + c * 12288, ntb, wm, lane, acc1);
        __syncthreads();
    }

    // register-resident GRU cell epilogue
    const int w16 = half * 4 + wn;
    const int jq = (lane & 3) * 2;
    const int lane4 = lane >> 2;

    float bir[2][2], biz[2][2], bin_[2][2];
    float bhr[2][2], bhz[2][2], bhn[2][2];
#pragma unroll
    for (int nb = 0; nb < 2; nb++)
#pragma unroll
        for (int ci = 0; ci < 2; ci++) {
            int j = w16 * 16 + nb * 8 + jq + ci;
            bir[nb][ci] = bih[j];        biz[nb][ci] = bih[128 + j];
            bin_[nb][ci] = bih[256 + j];
            bhr[nb][ci] = bhh[j];        bhz[nb][ci] = bhh[128 + j];
            bhn[nb][ci] = bhh[256 + j];
        }

#pragma unroll
    for (int m = 0; m < 2; m++) {
#pragma unroll
        for (int h8 = 0; h8 < 2; h8++) {
            int gm = mb + wm * 32 + m * 16 + lane4 + h8 * 8;
            int ob = gm / NNODE;
            int on = gm - ob * NNODE;
            size_t obase = WOUT ? ((size_t)((ob * TT + t) * NNODE + on) * HH) : 0;
#pragma unroll
            for (int nb = 0; nb < 2; nb++) {
                int j0 = w16 * 16 + nb * 8 + jq;
                float2 hp = *(const float2*)&Hin[(size_t)gm * HH + j0];
                float hv[2];
#pragma unroll
                for (int ci = 0; ci < 2; ci++) {
                    int c = h8 * 2 + ci;
                    float ir = acc0[m][nb][c]     + bir[nb][ci];
                    float iz = acc0[m][nb + 2][c] + biz[nb][ci];
                    float in_ = acc0[m][nb + 4][c] + bin_[nb][ci];
                    float hr = acc1[m][nb][c]     + bhr[nb][ci];
                    float hz = acc1[m][nb + 2][c] + bhz[nb][ci];
                    float hn = acc1[m][nb + 4][c] + bhn[nb][ci];
                    float r = 1.f / (1.f + __expf(-(ir + hr)));
                    float z = 1.f / (1.f + __expf(-(iz + hz)));
                    float nn = tanhf(in_ + r * hn);
                    float hpv = ci ? hp.y : hp.x;
                    hv[ci] = (1.f - z) * nn + z * hpv;
                }
                float2 hv2 = make_float2(hv[0], hv[1]);
                *(float2*)&Hout[(size_t)gm * HH + j0] = hv2;
                if (WOUT)
                    *(float2*)&Oout[obase + j0] = hv2;
            }
        }
    }
}

__device__ __forceinline__ void pair_sync() {
    __threadfence();   // membar.gl: publish my writes + IVALL my L1
    asm volatile("barrier.cluster.arrive.aligned;" ::: "memory");
    asm volatile("barrier.cluster.wait.aligned;" ::: "memory");
}

// persistent kernel: all 64 timesteps, both layers.
// grid (69, 2), cluster (1, 2): the two half-blocks of an m-block form a
// cluster; ALL data deps are within the pair, so only pairwise sync needed.
__global__ void __launch_bounds__(NTH, 1) __cluster_dims__(1, 2, 1)
gru_persist(const float* __restrict__ x,
            const float* __restrict__ bih0, const float* __restrict__ bhh0,
            const float* __restrict__ bih1, const float* __restrict__ bhh1,
            float* __restrict__ out)
{
    __shared__ unsigned sm[6144];   // 24KB

    const int tid = threadIdx.x;
    const int mb = blockIdx.x * MTILE;
    const int half = blockIdx.y;
    const int wid = tid >> 5, lane = tid & 31;
    const int wm = wid >> 2, wn = wid & 3;

    const uint2* wpb = (const uint2*)g_wp;

#pragma unroll 1
    for (int t = 0; t < TT; t++) {
        int cur = t & 1, nxt = cur ^ 1;
        run_layer<true, false>(sm, x, 64,
            &g_h0[cur][0], &g_h0[nxt][0], (float*)nullptr,
            wpb + WPU2_L0IH, wpb + WPU2_L0HH, bih0, bhh0,
            t, mb, half, wm, wn, lane, tid);
        pair_sync();
        run_layer<false, true>(sm, &g_h0[nxt][0], 128,
            &g_h1[cur][0], &g_h1[nxt][0], out,
            wpb + WPU2_L1IH, wpb + WPU2_L1HH, bih1, bhh1,
            t, mb, half, wm, wn, lane, tid);
        pair_sync();
    }
}

extern "C" void kernel_launch(void* const* d_in, const int* in_sizes, int n_in,
                              void* d_out, int out_size)
{
    const float* x    = (const float*)d_in[0];
    const float* Wih0 = (const float*)d_in[1];
    const float* Whh0 = (const float*)d_in[2];
    const float* bih0 = (const float*)d_in[3];
    const float* bhh0 = (const float*)d_in[4];
    const float* Wih1 = (const float*)d_in[5];
    const float* Whh1 = (const float*)d_in[6];
    const float* bih1 = (const float*)d_in[7];
    const float* bhh1 = (const float*)d_in[8];

    float* out = (float*)d_out;
    float* h0f = out + (size_t)BB * TT * NNODE * HH;
    float* h1f = h0f + (size_t)MM * HH;

    float *h0p = nullptr, *h1p = nullptr;
    cudaGetSymbolAddress((void**)&h0p, g_h0);
    cudaGetSymbolAddress((void**)&h1p, g_h1);
    const size_t SH = (size_t)MM * HH;

    prep_kernel<<<168, 256>>>(Wih0, Whh0, Wih1, Whh1);
    zero_states_kernel<<<(MM * HH + 255) / 256, 256>>>();

    gru_persist<<<dim3(GRIDM, 2), NTH>>>(x, bih0, bhh0, bih1, bhh1, out);

    // after t=63 (cur=1), fresh states live in buffer index 0
    cudaMemcpyAsync(h0f, h0p, SH * sizeof(float), cudaMemcpyDeviceToDevice);
    cudaMemcpyAsync(h1f, h1p, SH * sizeof(float), cudaMemcpyDeviceToDevice);
}

// round 8
// speedup vs baseline: 2.2754x; 1.0559x over previous
#include <cuda_runtime.h>
#include <cuda_bf16.h>
#include <cstdint>

#define BB 32
#define TT 64
#define NNODE 207
#define FF 64
#define HH 128
#define MM (BB * NNODE)      // 6624
#define MTILE 96
#define GRIDM 69             // 6624 / 96
#define NTH 384

// packed bf16 hi/lo weights, fragment-native (m16n8k16) layout.
// uint2 unit index: ((k16*48 + ntile)*2 + hilo)*32 + lane ; uint2 = {b0,b1}
#define WPU2_L0IH 0
#define WPU2_L0HH 12288      // 4*48*2*32
#define WPU2_L1IH 36864
#define WPU2_L1HH 61440
#define WPU2_TOTAL 86016
__device__ unsigned g_wp[WPU2_TOTAL * 2];

// smem layout (u32 units): XF[6144] | H0F[12288] | H1F[12288]  = 120KB
#define XF_OFF 0
#define H0F_OFF 6144
#define H1F_OFF 18432
#define SM_U32 30720

// ---------------- weight prepack (same layout as validated R6) ----------------
__global__ void prep_kernel(const float* __restrict__ Wih0, const float* __restrict__ Whh0,
                            const float* __restrict__ Wih1, const float* __restrict__ Whh1)
{
    __nv_bfloat16* wp = reinterpret_cast<__nv_bfloat16*>(g_wp);
    const float* srcs[4] = {Wih0, Whh0, Wih1, Whh1};
    const int Ks[4]   = {64, 128, 128, 128};
    const int offs[4] = {WPU2_L0IH * 4, WPU2_L0HH * 4, WPU2_L1IH * 4, WPU2_L1HH * 4};
    const int total = (64 + 128 + 128 + 128) * 384;
    for (int idx = blockIdx.x * blockDim.x + threadIdx.x; idx < total;
         idx += gridDim.x * blockDim.x) {
        int m, rem = idx;
        for (m = 0; m < 4; m++) {
            int sz = Ks[m] * 384;
            if (rem < sz) break;
            rem -= sz;
        }
        int k = rem / 384;
        int p = rem % 384;
        int w16 = p / 48, g = (p % 48) / 16, jj = p % 16;
        float v = srcs[m][(size_t)k * 384 + g * 128 + w16 * 16 + jj];
        __nv_bfloat16 hb = __float2bfloat16_rn(v);
        __nv_bfloat16 lb = __float2bfloat16_rn(v - __bfloat162float(hb));
        int k16 = k >> 4, kk = k & 15;
        int nt = p >> 3;
        int lane = (p & 7) * 4 + ((kk & 7) >> 1);
        int slot = kk >> 3;
        int hw = kk & 1;
        int ib = (((k16 * 48 + nt) * 2) * 32 + lane) * 4 + slot * 2 + hw;
        wp[offs[m] + ib] = hb;
        wp[offs[m] + ib + 128] = lb;
    }
}

#define MMA_B(D, A, B)                                                            \
    asm volatile(                                                                 \
        "mma.sync.aligned.m16n8k16.row.col.f32.bf16.bf16.f32 "                    \
        "{%0,%1,%2,%3},{%4,%5,%6,%7},{%8,%9},{%0,%1,%2,%3};\n"                    \
        : "+f"(D[0]), "+f"(D[1]), "+f"(D[2]), "+f"(D[3])                          \
        : "r"(A.x), "r"(A.y), "r"(A.z), "r"(A.w), "r"(B.x), "r"(B.y))

__device__ __forceinline__ void split_pack(float vx, float vy, unsigned& hi, unsigned& lo) {
    __nv_bfloat16 hx = __float2bfloat16_rn(vx);
    __nv_bfloat16 hy = __float2bfloat16_rn(vy);
    __nv_bfloat16 lx = __float2bfloat16_rn(vx - __bfloat162float(hx));
    __nv_bfloat16 ly = __float2bfloat16_rn(vy - __bfloat162float(hy));
    hi = (unsigned)__bfloat16_as_ushort(hx) | ((unsigned)__bfloat16_as_ushort(hy) << 16);
    lo = (unsigned)__bfloat16_as_ushort(lx) | ((unsigned)__bfloat16_as_ushort(ly) << 16);
}

__device__ __forceinline__ float2 unsplit(unsigned hi, unsigned lo) {
    float hx = __bfloat162float(__ushort_as_bfloat16((unsigned short)(hi & 0xffff)));
    float hy = __bfloat162float(__ushort_as_bfloat16((unsigned short)(hi >> 16)));
    float lx = __bfloat162float(__ushort_as_bfloat16((unsigned short)(lo & 0xffff)));
    float ly = __bfloat162float(__ushort_as_bfloat16((unsigned short)(lo >> 16)));
    return make_float2(hx + lx, hy + ly);
}

// load x[t] chunk (K=64 -> 4 k16) into XF in fragment-native form
__device__ __forceinline__ void load_x(unsigned* XF, const float* __restrict__ x,
                                       int mb, int t, int tid)
{
#pragma unroll
    for (int it = 0; it < 2; it++) {
        int s = tid + it * NTH;          // 0..767
        int ln = s & 31;
        int t2 = s >> 5;                 // ksl*6 + mt
        int mt = t2 % 6, ksl = t2 / 6;
        int r0 = mb + mt * 16 + (ln >> 2);
        int c0 = ksl * 16 + (ln & 3) * 2;
        int b0 = r0 / NNODE, n0 = r0 - b0 * NNODE;
        int r1 = r0 + 8;
        int b1 = r1 / NNODE, n1 = r1 - b1 * NNODE;
        const float* p0 = x + (size_t)((b0 * TT + t) * NNODE + n0) * FF;
        const float* p1 = x + (size_t)((b1 * TT + t) * NNODE + n1) * FF;
        float2 v00 = *(const float2*)(p0 + c0);
        float2 v01 = *(const float2*)(p0 + c0 + 8);
        float2 v10 = *(const float2*)(p1 + c0);
        float2 v11 = *(const float2*)(p1 + c0 + 8);
        unsigned h0, l0, h1, l1, h2, l2, h3, l3;
        split_pack(v00.x, v00.y, h0, l0);
        split_pack(v10.x, v10.y, h1, l1);
        split_pack(v01.x, v01.y, h2, l2);
        split_pack(v11.x, v11.y, h3, l3);
        *(uint4*)(XF + (t2 * 2 + 0) * 128 + ln * 4) = make_uint4(h0, h1, h2, h3);
        *(uint4*)(XF + (t2 * 2 + 1) * 128 + ln * 4) = make_uint4(l0, l1, l2, l3);
    }
}

// MMA over NK16 k16-steps: A from smem frag region, B from global weights
template <int NK16>
__device__ __forceinline__ void mma_span(const unsigned* af, const uint2* __restrict__ wb,
                                         int ntb, int wm, int lane, float (*acc)[6][4])
{
#pragma unroll
    for (int ks = 0; ks < NK16; ks++) {
        uint4 ah[2], al[2];
#pragma unroll
        for (int m = 0; m < 2; m++) {
            int t2 = ks * 6 + wm * 2 + m;
            ah[m] = *(const uint4*)(af + (t2 * 2 + 0) * 128 + lane * 4);
            al[m] = *(const uint4*)(af + (t2 * 2 + 1) * 128 + lane * 4);
        }
        uint2 bh[6], bl[6];
#pragma unroll
        for (int n = 0; n < 6; n++) {
            int i2 = ((ks * 48 + ntb + n) * 2) * 32 + lane;
            bh[n] = wb[i2];
            bl[n] = wb[i2 + 32];
        }
#pragma unroll
        for (int m = 0; m < 2; m++)
#pragma unroll
            for (int n = 0; n < 6; n++) {
                MMA_B(acc[m][n], ah[m], bh[n]);
                MMA_B(acc[m][n], ah[m], bl[n]);
                MMA_B(acc[m][n], al[m], bh[n]);
            }
    }
}

__device__ __forceinline__ void cluster_sync_() {
    __syncthreads();
    asm volatile("barrier.cluster.arrive.aligned;" ::: "memory");
    asm volatile("barrier.cluster.wait.aligned;" ::: "memory");
}

__device__ __forceinline__ void st_peer(unsigned peer_addr, unsigned v) {
    asm volatile("st.shared::cluster.u32 [%0], %1;" :: "r"(peer_addr), "r"(v) : "memory");
}

// GRU epilogue: compute h_new from acc0/acc1, write frags to own+peer HF,
// optionally out[t], optionally final-state fp32.
template <bool WOUT>
__device__ __forceinline__ void gru_epilogue(
    unsigned* HF, unsigned peerHF,      // own ptr, peer generic-shared u32 addr
    const float (*acc0)[6][4], const float (*acc1)[6][4],
    const float* __restrict__ bih, const float* __restrict__ bhh,
    float* __restrict__ Oout, float* __restrict__ Hfin,
    int t, int mb, int half, int wm, int wn, int lane, bool write_fin)
{
    const int w16 = half * 4 + wn;
    const int jq = (lane & 3) * 2;
    const int lane4 = lane >> 2;

#pragma unroll
    for (int m = 0; m < 2; m++) {
#pragma unroll
        for (int h8 = 0; h8 < 2; h8++) {
            int gm = mb + wm * 32 + m * 16 + lane4 + h8 * 8;
            int ob = gm / NNODE;
            int on = gm - ob * NNODE;
            size_t obase = WOUT ? ((size_t)((ob * TT + t) * NNODE + on) * HH) : 0;
#pragma unroll
            for (int nb = 0; nb < 2; nb++) {
                int j0 = w16 * 16 + nb * 8 + jq;
                // frag index for (row gm-local, cols j0..j0+1):
                int base = ((w16 * 6 + wm * 2 + m) * 2) * 128 + lane * 4 + (nb * 2 + h8);
                float2 hp = unsplit(HF[base], HF[base + 128]);
                int c = h8 * 2; // acc col-slot base for this h8
                float hv[2];
#pragma unroll
                for (int ci = 0; ci < 2; ci++) {
                    int j = j0 + ci;
                    float ir = acc0[m][nb][c + ci]     + bih[j];
                    float iz = acc0[m][nb + 2][c + ci] + bih[128 + j];
                    float in_ = acc0[m][nb + 4][c + ci] + bih[256 + j];
                    float hr = acc1[m][nb][c + ci]     + bhh[j];
                    float hz = acc1[m][nb + 2][c + ci] + bhh[128 + j];
                    float hn = acc1[m][nb + 4][c + ci] + bhh[256 + j];
                    float r = 1.f / (1.f + __expf(-(ir + hr)));
                    float z = 1.f / (1.f + __expf(-(iz + hz)));
                    float nn = tanhf(in_ + r * hn);
                    float hpv = ci ? hp.y : hp.x;
                    hv[ci] = (1.f - z) * nn + z * hpv;
                }
                unsigned hi, lo;
                split_pack(hv[0], hv[1], hi, lo);
                HF[base] = hi;
                HF[base + 128] = lo;
                st_peer(peerHF + base * 4, hi);
                st_peer(peerHF + (base + 128) * 4, lo);
                if (WOUT)
                    *(float2*)&Oout[obase + j0] = make_float2(hv[0], hv[1]);
                if (write_fin)
                    *(float2*)&Hfin[(size_t)gm * HH + j0] = make_float2(hv[0], hv[1]);
            }
        }
    }
}

// persistent kernel: all 64 timesteps, both layers; H state lives in smem frags.
__global__ void __launch_bounds__(NTH, 1) __cluster_dims__(1, 2, 1)
gru_persist(const float* __restrict__ x,
            const float* __restrict__ bih0, const float* __restrict__ bhh0,
            const float* __restrict__ bih1, const float* __restrict__ bhh1,
            float* __restrict__ out, float* __restrict__ h0f, float* __restrict__ h1f)
{
    extern __shared__ unsigned sm[];
    unsigned* XF = sm + XF_OFF;
    unsigned* H0F = sm + H0F_OFF;
    unsigned* H1F = sm + H1F_OFF;

    const int tid = threadIdx.x;
    const int mb = blockIdx.x * MTILE;
    const int half = blockIdx.y;
    const int wid = tid >> 5, lane = tid & 31;
    const int wm = wid >> 2, wn = wid & 3;
    const int ntb = half * 24 + wn * 6;

    // peer generic-shared base addresses for H0F/H1F
    unsigned my_h0, peer_h0, my_h1, peer_h1, rank;
    asm("mov.u32 %0, %%cluster_ctarank;" : "=r"(rank));
    {
        unsigned a0, a1;
        asm("{ .reg .u64 t; cvta.to.shared.u64 t, %1; cvt.u32.u64 %0, t; }"
            : "=r"(a0) : "l"(H0F));
        asm("{ .reg .u64 t; cvta.to.shared.u64 t, %1; cvt.u32.u64 %0, t; }"
            : "=r"(a1) : "l"(H1F));
        my_h0 = a0; my_h1 = a1;
        unsigned pr = rank ^ 1;
        asm("mapa.shared::cluster.u32 %0, %1, %2;" : "=r"(peer_h0) : "r"(my_h0), "r"(pr));
        asm("mapa.shared::cluster.u32 %0, %1, %2;" : "=r"(peer_h1) : "r"(my_h1), "r"(pr));
    }

    // init: h0 = h1 = 0
    for (int i = tid; i < 24576; i += NTH) H0F[i] = 0u;
    __syncthreads();

    const uint2* wpb = (const uint2*)g_wp;
    const uint2* w0ih = wpb + WPU2_L0IH;
    const uint2* w0hh = wpb + WPU2_L0HH;
    const uint2* w1ih = wpb + WPU2_L1IH;
    const uint2* w1hh = wpb + WPU2_L1HH;

#pragma unroll 1
    for (int t = 0; t < TT; t++) {
        // ---- stage x[t] ----
        load_x(XF, x, mb, t, tid);
        __syncthreads();

        // ---- layer 0 ----
        {
            float acc0[2][6][4], acc1[2][6][4];
#pragma unroll
            for (int m = 0; m < 2; m++)
#pragma unroll
                for (int n = 0; n < 6; n++)
#pragma unroll
                    for (int c = 0; c < 4; c++) { acc0[m][n][c] = 0.f; acc1[m][n][c] = 0.f; }
            mma_span<4>(XF, w0ih, ntb, wm, lane, acc0);
            mma_span<8>(H0F, w0hh, ntb, wm, lane, acc1);
            cluster_sync_();                             // B1: peers done reading old H0F
            gru_epilogue<false>(H0F, peer_h0, acc0, acc1, bih0, bhh0,
                                (float*)nullptr, h0f, t, mb, half, wm, wn, lane, t == TT - 1);
            cluster_sync_();                             // B2: new H0F visible
        }

        // ---- layer 1 ----
        {
            float acc0[2][6][4], acc1[2][6][4];
#pragma unroll
            for (int m = 0; m < 2; m++)
#pragma unroll
                for (int n = 0; n < 6; n++)
#pragma unroll
                    for (int c = 0; c < 4; c++) { acc0[m][n][c] = 0.f; acc1[m][n][c] = 0.f; }
            mma_span<8>(H0F, w1ih, ntb, wm, lane, acc0);
            mma_span<8>(H1F, w1hh, ntb, wm, lane, acc1);
            cluster_sync_();                             // B3: peers done reading old H1F
            gru_epilogue<true>(H1F, peer_h1, acc0, acc1, bih1, bhh1,
                               out, h1f, t, mb, half, wm, wn, lane, t == TT - 1);
            // epi1 writes ordered for peer by next step's B1+B2
        }
    }

    // FINAL cluster barrier: no CTA may exit while the peer's
    // st.shared::cluster writes into this CTA's smem may be in flight.
    cluster_sync_();
}

extern "C" void kernel_launch(void* const* d_in, const int* in_sizes, int n_in,
                              void* d_out, int out_size)
{
    const float* x    = (const float*)d_in[0];
    const float* Wih0 = (const float*)d_in[1];
    const float* Whh0 = (const float*)d_in[2];
    const float* bih0 = (const float*)d_in[3];
    const float* bhh0 = (const float*)d_in[4];
    const float* Wih1 = (const float*)d_in[5];
    const float* Whh1 = (const float*)d_in[6];
    const float* bih1 = (const float*)d_in[7];
    const float* bhh1 = (const float*)d_in[8];

    float* out = (float*)d_out;
    float* h0f = out + (size_t)BB * TT * NNODE * HH;
    float* h1f = h0f + (size_t)MM * HH;

    cudaFuncSetAttribute((const void*)gru_persist,
                         cudaFuncAttributeMaxDynamicSharedMemorySize, SM_U32 * 4);

    prep_kernel<<<168, 256>>>(Wih0, Whh0, Wih1, Whh1);
    gru_persist<<<dim3(GRIDM, 2), NTH, SM_U32 * 4>>>(
        x, bih0, bhh0, bih1, bhh1, out, h0f, h1f);
}

// round 10
// speedup vs baseline: 2.4009x; 1.0552x over previous
#include <cuda_runtime.h>
#include <cuda_bf16.h>
#include <cstdint>

#define BB 32
#define TT 64
#define NNODE 207
#define FF 64
#define HH 128
#define MM (BB * NNODE)      // 6624
#define MTILE 96
#define GRIDM 69             // 6624 / 96
#define NTH 384

// packed bf16 hi/lo weights, fragment-native (m16n8k16) layout.
// uint2 unit index: ((k16*48 + ntile)*2 + hilo)*32 + lane ; uint2 = {b0,b1}
#define WPU2_L0IH 0
#define WPU2_L0HH 12288      // 4*48*2*32
#define WPU2_L1IH 36864
#define WPU2_L1HH 61440
#define WPU2_TOTAL 86016
__device__ unsigned g_wp[WPU2_TOTAL * 2];

// smem layout (u32 units): XF[6144] | H0F[12288] | H1F[12288] | BIAS[1536]
#define XF_OFF 0
#define H0F_OFF 6144
#define H1F_OFF 18432
#define BIAS_OFF 30720       // 4 x 384 floats: bih0, bhh0, bih1, bhh1
#define SM_U32 32256         // 126KB

// ---------------- weight prepack (same layout as validated R6/R8) ----------------
__global__ void prep_kernel(const float* __restrict__ Wih0, const float* __restrict__ Whh0,
                            const float* __restrict__ Wih1, const float* __restrict__ Whh1)
{
    __nv_bfloat16* wp = reinterpret_cast<__nv_bfloat16*>(g_wp);
    const float* srcs[4] = {Wih0, Whh0, Wih1, Whh1};
    const int Ks[4]   = {64, 128, 128, 128};
    const int offs[4] = {WPU2_L0IH * 4, WPU2_L0HH * 4, WPU2_L1IH * 4, WPU2_L1HH * 4};
    const int total = (64 + 128 + 128 + 128) * 384;
    for (int idx = blockIdx.x * blockDim.x + threadIdx.x; idx < total;
         idx += gridDim.x * blockDim.x) {
        int m, rem = idx;
        for (m = 0; m < 4; m++) {
            int sz = Ks[m] * 384;
            if (rem < sz) break;
            rem -= sz;
        }
        int k = rem / 384;
        int p = rem % 384;
        int w16 = p / 48, g = (p % 48) / 16, jj = p % 16;
        float v = srcs[m][(size_t)k * 384 + g * 128 + w16 * 16 + jj];
        __nv_bfloat16 hb = __float2bfloat16_rn(v);
        __nv_bfloat16 lb = __float2bfloat16_rn(v - __bfloat162float(hb));
        int k16 = k >> 4, kk = k & 15;
        int nt = p >> 3;
        int lane = (p & 7) * 4 + ((kk & 7) >> 1);
        int slot = kk >> 3;
        int hw = kk & 1;
        int ib = (((k16 * 48 + nt) * 2) * 32 + lane) * 4 + slot * 2 + hw;
        wp[offs[m] + ib] = hb;
        wp[offs[m] + ib + 128] = lb;
    }
}

#define MMA_B(D, A, B)                                                            \
    asm volatile(                                                                 \
        "mma.sync.aligned.m16n8k16.row.col.f32.bf16.bf16.f32 "                    \
        "{%0,%1,%2,%3},{%4,%5,%6,%7},{%8,%9},{%0,%1,%2,%3};\n"                    \
        : "+f"(D[0]), "+f"(D[1]), "+f"(D[2]), "+f"(D[3])                          \
        : "r"(A.x), "r"(A.y), "r"(A.z), "r"(A.w), "r"(B.x), "r"(B.y))

__device__ __forceinline__ void split_pack(float vx, float vy, unsigned& hi, unsigned& lo) {
    __nv_bfloat16 hx = __float2bfloat16_rn(vx);
    __nv_bfloat16 hy = __float2bfloat16_rn(vy);
    __nv_bfloat16 lx = __float2bfloat16_rn(vx - __bfloat162float(hx));
    __nv_bfloat16 ly = __float2bfloat16_rn(vy - __bfloat162float(hy));
    hi = (unsigned)__bfloat16_as_ushort(hx) | ((unsigned)__bfloat16_as_ushort(hy) << 16);
    lo = (unsigned)__bfloat16_as_ushort(lx) | ((unsigned)__bfloat16_as_ushort(ly) << 16);
}

__device__ __forceinline__ float2 unsplit(unsigned hi, unsigned lo) {
    float hx = __bfloat162float(__ushort_as_bfloat16((unsigned short)(hi & 0xffff)));
    float hy = __bfloat162float(__ushort_as_bfloat16((unsigned short)(hi >> 16)));
    float lx = __bfloat162float(__ushort_as_bfloat16((unsigned short)(lo & 0xffff)));
    float ly = __bfloat162float(__ushort_as_bfloat16((unsigned short)(lo >> 16)));
    return make_float2(hx + lx, hy + ly);
}

// fast sigmoid / tanh (MUFU-based; ~1e-6 rel error, saturates correctly)
__device__ __forceinline__ float fsigmoid(float x) {
    return __fdividef(1.f, 1.f + __expf(-x));
}
__device__ __forceinline__ float ftanh(float x) {
    return __fdividef(2.f, 1.f + __expf(-2.f * x)) - 1.f;
}

// load x[t] chunk (K=64 -> 4 k16) into XF in fragment-native form
__device__ __forceinline__ void load_x(unsigned* XF, const float* __restrict__ x,
                                       int mb, int t, int tid)
{
#pragma unroll
    for (int it = 0; it < 2; it++) {
        int s = tid + it * NTH;          // 0..767
        int ln = s & 31;
        int t2 = s >> 5;                 // ksl*6 + mt
        int mt = t2 % 6, ksl = t2 / 6;
        int r0 = mb + mt * 16 + (ln >> 2);
        int c0 = ksl * 16 + (ln & 3) * 2;
        int b0 = r0 / NNODE, n0 = r0 - b0 * NNODE;
        int r1 = r0 + 8;
        int b1 = r1 / NNODE, n1 = r1 - b1 * NNODE;
        const float* p0 = x + (size_t)((b0 * TT + t) * NNODE + n0) * FF;
        const float* p1 = x + (size_t)((b1 * TT + t) * NNODE + n1) * FF;
        float2 v00 = *(const float2*)(p0 + c0);
        float2 v01 = *(const float2*)(p0 + c0 + 8);
        float2 v10 = *(const float2*)(p1 + c0);
        float2 v11 = *(const float2*)(p1 + c0 + 8);
        unsigned h0, l0, h1, l1, h2, l2, h3, l3;
        split_pack(v00.x, v00.y, h0, l0);
        split_pack(v10.x, v10.y, h1, l1);
        split_pack(v01.x, v01.y, h2, l2);
        split_pack(v11.x, v11.y, h3, l3);
        *(uint4*)(XF + (t2 * 2 + 0) * 128 + ln * 4) = make_uint4(h0, h1, h2, h3);
        *(uint4*)(XF + (t2 * 2 + 1) * 128 + ln * 4) = make_uint4(l0, l1, l2, l3);
    }
}

// MMA over NK16 k16-steps: A from smem frag region, B from global weights
template <int NK16>
__device__ __forceinline__ void mma_span(const unsigned* af, const uint2* __restrict__ wb,
                                         int ntb, int wm, int lane, float (*acc)[6][4])
{
#pragma unroll
    for (int ks = 0; ks < NK16; ks++) {
        uint4 ah[2], al[2];
#pragma unroll
        for (int m = 0; m < 2; m++) {
            int t2 = ks * 6 + wm * 2 + m;
            ah[m] = *(const uint4*)(af + (t2 * 2 + 0) * 128 + lane * 4);
            al[m] = *(const uint4*)(af + (t2 * 2 + 1) * 128 + lane * 4);
        }
        uint2 bh[6], bl[6];
#pragma unroll
        for (int n = 0; n < 6; n++) {
            int i2 = ((ks * 48 + ntb + n) * 2) * 32 + lane;
            bh[n] = wb[i2];
            bl[n] = wb[i2 + 32];
        }
#pragma unroll
        for (int m = 0; m < 2; m++)
#pragma unroll
            for (int n = 0; n < 6; n++) {
                MMA_B(acc[m][n], ah[m], bh[n]);
                MMA_B(acc[m][n], ah[m], bl[n]);
                MMA_B(acc[m][n], al[m], bh[n]);
            }
    }
}

__device__ __forceinline__ void cluster_sync_() {
    __syncthreads();
    asm volatile("barrier.cluster.arrive.aligned;" ::: "memory");
    asm volatile("barrier.cluster.wait.aligned;" ::: "memory");
}

__device__ __forceinline__ void st_peer(unsigned peer_addr, unsigned v) {
    asm volatile("st.shared::cluster.u32 [%0], %1;" :: "r"(peer_addr), "r"(v) : "memory");
}

// GRU epilogue: compute h_new from acc0/acc1, write frags to own+peer HF,
// optionally out[t], optionally final-state fp32. Biases come from smem.
template <bool WOUT>
__device__ __forceinline__ void gru_epilogue(
    unsigned* HF, unsigned peerHF,
    const float (*acc0)[6][4], const float (*acc1)[6][4],
    const float* __restrict__ bi, const float* __restrict__ bh,   // smem, 384 each
    float* __restrict__ Oout, float* __restrict__ Hfin,
    int t, int mb, int half, int wm, int wn, int lane, bool write_fin)
{
    const int w16 = half * 4 + wn;
    const int jq = (lane & 3) * 2;
    const int lane4 = lane >> 2;

    // hoist biases for this thread's 4 j's (nb, ci): 24 regs
    float BI[3][2][2], BH[3][2][2];
#pragma unroll
    for (int nb = 0; nb < 2; nb++)
#pragma unroll
        for (int ci = 0; ci < 2; ci++) {
            int j = w16 * 16 + nb * 8 + jq + ci;
            BI[0][nb][ci] = bi[j];       BI[1][nb][ci] = bi[128 + j];
            BI[2][nb][ci] = bi[256 + j];
            BH[0][nb][ci] = bh[j];       BH[1][nb][ci] = bh[128 + j];
            BH[2][nb][ci] = bh[256 + j];
        }

#pragma unroll
    for (int m = 0; m < 2; m++) {
#pragma unroll
        for (int h8 = 0; h8 < 2; h8++) {
            int gm = mb + wm * 32 + m * 16 + lane4 + h8 * 8;
            int ob = gm / NNODE;
            int on = gm - ob * NNODE;
            size_t obase = WOUT ? ((size_t)((ob * TT + t) * NNODE + on) * HH) : 0;
#pragma unroll
            for (int nb = 0; nb < 2; nb++) {
                int j0 = w16 * 16 + nb * 8 + jq;
                int base = ((w16 * 6 + wm * 2 + m) * 2) * 128 + lane * 4 + (nb * 2 + h8);
                float2 hp = unsplit(HF[base], HF[base + 128]);
                int c = h8 * 2;
                float hv[2];
#pragma unroll
                for (int ci = 0; ci < 2; ci++) {
                    float ir = acc0[m][nb][c + ci]     + BI[0][nb][ci];
                    float iz = acc0[m][nb + 2][c + ci] + BI[1][nb][ci];
                    float in_ = acc0[m][nb + 4][c + ci] + BI[2][nb][ci];
                    float hr = acc1[m][nb][c + ci]     + BH[0][nb][ci];
                    float hz = acc1[m][nb + 2][c + ci] + BH[1][nb][ci];
                    float hn = acc1[m][nb + 4][c + ci] + BH[2][nb][ci];
                    float r = fsigmoid(ir + hr);
                    float z = fsigmoid(iz + hz);
                    float nn = ftanh(in_ + r * hn);
                    float hpv = ci ? hp.y : hp.x;
                    hv[ci] = (1.f - z) * nn + z * hpv;
                }
                unsigned hi, lo;
                split_pack(hv[0], hv[1], hi, lo);
                HF[base] = hi;
                HF[base + 128] = lo;
                st_peer(peerHF + base * 4, hi);
                st_peer(peerHF + (base + 128) * 4, lo);
                if (WOUT)
                    *(float2*)&Oout[obase + j0] = make_float2(hv[0], hv[1]);
                if (write_fin)
                    *(float2*)&Hfin[(size_t)gm * HH + j0] = make_float2(hv[0], hv[1]);
            }
        }
    }
}

// persistent kernel: all 64 timesteps, both layers; H state lives in smem frags.
__global__ void __launch_bounds__(NTH, 1) __cluster_dims__(1, 2, 1)
gru_persist(const float* __restrict__ x,
            const float* __restrict__ bih0, const float* __restrict__ bhh0,
            const float* __restrict__ bih1, const float* __restrict__ bhh1,
            float* __restrict__ out, float* __restrict__ h0f, float* __restrict__ h1f)
{
    extern __shared__ unsigned sm[];
    unsigned* XF = sm + XF_OFF;
    unsigned* H0F = sm + H0F_OFF;
    unsigned* H1F = sm + H1F_OFF;
    float* BS = (float*)(sm + BIAS_OFF);   // [bih0 | bhh0 | bih1 | bhh1]

    const int tid = threadIdx.x;
    const int mb = blockIdx.x * MTILE;
    const int half = blockIdx.y;
    const int wid = tid >> 5, lane = tid & 31;
    const int wm = wid >> 2, wn = wid & 3;
    const int ntb = half * 24 + wn * 6;

    // peer generic-shared base addresses for H0F/H1F
    unsigned peer_h0, peer_h1, rank;
    asm("mov.u32 %0, %%cluster_ctarank;" : "=r"(rank));
    {
        unsigned a0, a1;
        asm("{ .reg .u64 t; cvta.to.shared.u64 t, %1; cvt.u32.u64 %0, t; }"
            : "=r"(a0) : "l"(H0F));
        asm("{ .reg .u64 t; cvta.to.shared.u64 t, %1; cvt.u32.u64 %0, t; }"
            : "=r"(a1) : "l"(H1F));
        unsigned pr = rank ^ 1;
        asm("mapa.shared::cluster.u32 %0, %1, %2;" : "=r"(peer_h0) : "r"(a0), "r"(pr));
        asm("mapa.shared::cluster.u32 %0, %1, %2;" : "=r"(peer_h1) : "r"(a1), "r"(pr));
    }

    // init: h0 = h1 = 0 ; stage biases to smem
    for (int i = tid; i < 24576; i += NTH) H0F[i] = 0u;
    for (int i = tid; i < 384; i += NTH) {
        BS[i]        = bih0[i];
        BS[384 + i]  = bhh0[i];
        BS[768 + i]  = bih1[i];
        BS[1152 + i] = bhh1[i];
    }
    __syncthreads();

    const uint2* wpb = (const uint2*)g_wp;
    const uint2* w0ih = wpb + WPU2_L0IH;
    const uint2* w0hh = wpb + WPU2_L0HH;
    const uint2* w1ih = wpb + WPU2_L1IH;
    const uint2* w1hh = wpb + WPU2_L1HH;

#pragma unroll 1
    for (int t = 0; t < TT; t++) {
        // ---- stage x[t] ----
        load_x(XF, x, mb, t, tid);
        __syncthreads();

        // ---- layer 0 ----
        {
            float acc0[2][6][4], acc1[2][6][4];
#pragma unroll
            for (int m = 0; m < 2; m++)
#pragma unroll
                for (int n = 0; n < 6; n++)
#pragma unroll
                    for (int c = 0; c < 4; c++) { acc0[m][n][c] = 0.f; acc1[m][n][c] = 0.f; }
            mma_span<4>(XF, w0ih, ntb, wm, lane, acc0);
            mma_span<8>(H0F, w0hh, ntb, wm, lane, acc1);
            cluster_sync_();                             // B1: peers done reading old H0F
            gru_epilogue<false>(H0F, peer_h0, acc0, acc1, BS, BS + 384,
                                (float*)nullptr, h0f, t, mb, half, wm, wn, lane, t == TT - 1);
            cluster_sync_();                             // B2: new H0F visible
        }

        // ---- layer 1 ----
        {
            float acc0[2][6][4], acc1[2][6][4];
#pragma unroll
            for (int m = 0; m < 2; m++)
#pragma unroll
                for (int n = 0; n < 6; n++)
#pragma unroll
                    for (int c = 0; c < 4; c++) { acc0[m][n][c] = 0.f; acc1[m][n][c] = 0.f; }
            mma_span<8>(H0F, w1ih, ntb, wm, lane, acc0);
            mma_span<8>(H1F, w1hh, ntb, wm, lane, acc1);
            cluster_sync_();                             // B3: peers done reading old H1F
            gru_epilogue<true>(H1F, peer_h1, acc0, acc1, BS + 768, BS + 1152,
                               out, h1f, t, mb, half, wm, wn, lane, t == TT - 1);
            // epi1 writes ordered for peer by next step's B1+B2
        }
    }

    // FINAL cluster barrier: no CTA may exit while the peer's
    // st.shared::cluster writes into this CTA's smem may be in flight.
    cluster_sync_();
}

extern "C" void kernel_launch(void* const* d_in, const int* in_sizes, int n_in,
                              void* d_out, int out_size)
{
    const float* x    = (const float*)d_in[0];
    const float* Wih0 = (const float*)d_in[1];
    const float* Whh0 = (const float*)d_in[2];
    const float* bih0 = (const float*)d_in[3];
    const float* bhh0 = (const float*)d_in[4];
    const float* Wih1 = (const float*)d_in[5];
    const float* Whh1 = (const float*)d_in[6];
    const float* bih1 = (const float*)d_in[7];
    const float* bhh1 = (const float*)d_in[8];

    float* out = (float*)d_out;
    float* h0f = out + (size_t)BB * TT * NNODE * HH;
    float* h1f = h0f + (size_t)MM * HH;

    cudaFuncSetAttribute((const void*)gru_persist,
                         cudaFuncAttributeMaxDynamicSharedMemorySize, SM_U32 * 4);

    prep_kernel<<<168, 256>>>(Wih0, Whh0, Wih1, Whh1);
    gru_persist<<<dim3(GRIDM, 2), NTH, SM_U32 * 4>>>(
        x, bih0, bhh0, bih1, bhh1, out, h0f, h1f);
}